// round 5
// baseline (speedup 1.0000x reference)
#include <cuda_runtime.h>
#include <math.h>

// Problem constants (fixed shapes for this problem instance).
#define BB 4
#define NN 4096
#define MM 8192
#define CC 64

// Binning over the 1D coordinate. Data ~ N(0,10^2) so [-64,64) covers
// everything with huge margin; values outside are clamped to edge bins
// (harmless: only affects pairs separated by >> cutoff radius).
#define NBINS 1024
#define BIN_LO (-64.0f)
#define BIN_W  0.125f
#define BIN_INVW 8.0f

// ---------------- scratch (no allocations allowed -> device globals) -------
__device__ int   g_qcnt [BB][NBINS];
__device__ int   g_pcnt [BB][NBINS];
__device__ int   g_qcur [BB][NBINS];
__device__ int   g_pcur [BB][NBINS];
__device__ int   g_qstart[BB][NBINS + 1];
__device__ int   g_pstart[BB][NBINS + 1];
__device__ int   g_qperm[BB][NN];
__device__ float g_qx   [BB][NN];
__device__ int   g_pperm[BB][MM];
__device__ float g_px   [BB][MM];
// z gathered into sorted-point order and transposed to [B, M, C] (8 MB).
__device__ __align__(16) float g_zs[BB][MM][CC];

__device__ __forceinline__ int coord_bin(float v) {
    int b = (int)floorf((v - BIN_LO) * BIN_INVW);
    b = b < 0 ? 0 : b;
    b = b > (NBINS - 1) ? (NBINS - 1) : b;
    return b;
}

// ---------------- K1: zero counters ----------------------------------------
__global__ void k_zero() {
    int i = blockIdx.x * blockDim.x + threadIdx.x;
    if (i < BB * NBINS) {
        (&g_qcnt[0][0])[i] = 0;
        (&g_pcnt[0][0])[i] = 0;
        (&g_qcur[0][0])[i] = 0;
        (&g_pcur[0][0])[i] = 0;
    }
}

// ---------------- K2: histogram bins ----------------------------------------
__global__ void k_count_q(const float* __restrict__ x) {
    int i = blockIdx.x * blockDim.x + threadIdx.x;
    if (i < BB * NN) {
        int b = i / NN;
        atomicAdd(&g_qcnt[b][coord_bin(x[i])], 1);
    }
}
__global__ void k_count_p(const float* __restrict__ xz) {
    int i = blockIdx.x * blockDim.x + threadIdx.x;
    if (i < BB * MM) {
        int b = i / MM;
        atomicAdd(&g_pcnt[b][coord_bin(xz[i])], 1);
    }
}

// ---------------- K3: exclusive scan per (batch, array) --------------------
// 2*BB blocks of NBINS threads; Hillis-Steele inclusive scan in smem.
__global__ void k_scan() {
    __shared__ int sh[NBINS];
    int which = blockIdx.x;          // 0..2*BB-1
    int b  = which % BB;
    bool isq = (which < BB);
    const int* cnt = isq ? g_qcnt[b] : g_pcnt[b];
    int*       st  = isq ? g_qstart[b] : g_pstart[b];
    int t = threadIdx.x;
    sh[t] = cnt[t];
    __syncthreads();
    for (int off = 1; off < NBINS; off <<= 1) {
        int add = (t >= off) ? sh[t - off] : 0;
        __syncthreads();
        sh[t] += add;
        __syncthreads();
    }
    st[t + 1] = sh[t];
    if (t == 0) st[0] = 0;
}

// ---------------- K4: scatter into sorted order -----------------------------
__global__ void k_scatter_q(const float* __restrict__ x) {
    int i = blockIdx.x * blockDim.x + threadIdx.x;
    if (i < BB * NN) {
        int b = i / NN, n = i % NN;
        float v = x[i];
        int bn = coord_bin(v);
        int pos = g_qstart[b][bn] + atomicAdd(&g_qcur[b][bn], 1);
        g_qx[b][pos]   = v;
        g_qperm[b][pos] = n;
    }
}
__global__ void k_scatter_p(const float* __restrict__ xz) {
    int i = blockIdx.x * blockDim.x + threadIdx.x;
    if (i < BB * MM) {
        int b = i / MM, m = i % MM;
        float v = xz[i];
        int bn = coord_bin(v);
        int pos = g_pstart[b][bn] + atomicAdd(&g_pcur[b][bn], 1);
        g_px[b][pos]   = v;
        g_pperm[b][pos] = m;
    }
}

// ---------------- K5: gather z into [B, M_sorted, C] -------------------------
// z is [B, C, M]; thread handles one sorted point, reads 64 strided scalars
// (within-warp the original indices are random but each (b,c) slice is only
// 32 KB -> stays hot in L2), writes one contiguous 256B row.
__global__ void k_gather_z(const float* __restrict__ z) {
    int i = blockIdx.x * blockDim.x + threadIdx.x;
    if (i >= BB * MM) return;
    int b = i / MM, ms = i % MM;
    int mo = g_pperm[b][ms];
    const float* zb = z + (size_t)b * CC * MM + mo;
    float* dst = g_zs[b][ms];
#pragma unroll
    for (int c = 0; c < CC; c++) {
        dst[c] = zb[(size_t)c * MM];
    }
}

// ---------------- K6: main RBF-gather kernel --------------------------------
// One warp = 32 spatially-adjacent sorted queries. All lanes scan the same
// candidate point range [plo, phi): the px load and the 16x LDG.128 of the
// z row are warp-uniform (broadcast), so memory cost is ~1 line-set per point
// per warp and the loop is FFMA-issue bound.
__global__ void __launch_bounds__(128) k_main(const float* __restrict__ log_scale,
                                              float* __restrict__ out) {
    int gw   = (blockIdx.x * blockDim.x + threadIdx.x) >> 5;
    int lane = threadIdx.x & 31;
    if (gw >= BB * (NN / 32)) return;
    int b = gw / (NN / 32);
    int q = (gw % (NN / 32)) * 32 + lane;

    float ls = *log_scale;
    float s  = __expf(ls);
    float coef = -0.5f / (s * s);        // w = exp(coef * d^2)
    float R = 8.0f * s;                  // cutoff: weight <= exp(-32) ~ 1e-14
    int kb = (int)(R * BIN_INVW) + 1;    // bins to each side

    float xq = g_qx[b][q];
    int bq = coord_bin(xq);
    // queries are sorted by bin -> lane 0 has min bin, lane 31 max bin
    int bmin = __shfl_sync(0xffffffffu, bq, 0);
    int bmax = __shfl_sync(0xffffffffu, bq, 31);
    int blo = bmin - kb; blo = blo < 0 ? 0 : blo;
    int bhi = bmax + kb; bhi = bhi > (NBINS - 1) ? (NBINS - 1) : bhi;
    int plo = g_pstart[b][blo];
    int phi = g_pstart[b][bhi + 1];

    float4 acc[CC / 4];
#pragma unroll
    for (int j = 0; j < CC / 4; j++) acc[j] = make_float4(0.f, 0.f, 0.f, 0.f);

    for (int p = plo; p < phi; p++) {
        float xp = g_px[b][p];           // warp-uniform broadcast
        float d  = xq - xp;
        float w  = __expf(coef * d * d);
        const float4* zp = (const float4*)g_zs[b][p];  // warp-uniform row
#pragma unroll
        for (int j = 0; j < CC / 4; j++) {
            float4 v = zp[j];
            acc[j].x = fmaf(w, v.x, acc[j].x);
            acc[j].y = fmaf(w, v.y, acc[j].y);
            acc[j].z = fmaf(w, v.z, acc[j].z);
            acc[j].w = fmaf(w, v.w, acc[j].w);
        }
    }

    int norig = g_qperm[b][q];
    float4* o4 = (float4*)(out + ((size_t)b * NN + norig) * CC);
#pragma unroll
    for (int j = 0; j < CC / 4; j++) o4[j] = acc[j];
}

// ---------------- launch ------------------------------------------------------
extern "C" void kernel_launch(void* const* d_in, const int* in_sizes, int n_in,
                              void* d_out, int out_size) {
    const float* xz = (const float*)d_in[0];   // [B, M, 1]
    const float* z  = (const float*)d_in[1];   // [B, C, M]
    const float* x  = (const float*)d_in[2];   // [B, N, 1]
    const float* ls = (const float*)d_in[3];   // scalar
    float* out = (float*)d_out;                // [B, N, C]

    (void)in_sizes; (void)n_in; (void)out_size;

    k_zero<<<(BB * NBINS + 255) / 256, 256>>>();
    k_count_q<<<(BB * NN + 255) / 256, 256>>>(x);
    k_count_p<<<(BB * MM + 255) / 256, 256>>>(xz);
    k_scan<<<2 * BB, NBINS>>>();
    k_scatter_q<<<(BB * NN + 255) / 256, 256>>>(x);
    k_scatter_p<<<(BB * MM + 255) / 256, 256>>>(xz);
    k_gather_z<<<(BB * MM + 127) / 128, 128>>>(z);
    k_main<<<(BB * NN + 127) / 128, 128>>>(ls, out);
}

// round 6
// speedup vs baseline: 3.4392x; 3.4392x over previous
#include <cuda_runtime.h>
#include <math.h>
#include <stdint.h>

// Problem constants (fixed shapes for this problem instance).
#define BB 4
#define NN 4096
#define MM 8192
#define CC 64

// Binning over the 1D coordinate. Data ~ N(0,10^2) so [-64,64) covers
// everything; values outside are clamped to edge bins (harmless: only
// affects pairs separated by >> cutoff radius).
#define NBINS 1024
#define BIN_LO (-64.0f)
#define BIN_INVW 8.0f

// Main-kernel tiling.
#define QPB 32              // sorted queries per block
#define CG  4               // channel groups of 16 channels
#define TPB (QPB * CG)      // 128 threads
#define PT  64              // candidate points per smem tile

// ---------------- scratch (no allocations allowed -> device globals) -------
__device__ int   g_qcnt [BB][NBINS];
__device__ int   g_pcnt [BB][NBINS];
__device__ int   g_qcur [BB][NBINS];
__device__ int   g_pcur [BB][NBINS];
__device__ int   g_qstart[BB][NBINS + 1];
__device__ int   g_pstart[BB][NBINS + 1];
__device__ int   g_qperm[BB][NN];
__device__ float g_qx   [BB][NN];
__device__ int   g_pperm[BB][MM];
__device__ float g_px   [BB][MM];
// z gathered into sorted-point order and transposed to [B, M, C] (8 MB).
__device__ __align__(16) float g_zs[BB][MM][CC];

__device__ __forceinline__ int coord_bin(float v) {
    int b = (int)floorf((v - BIN_LO) * BIN_INVW);
    b = b < 0 ? 0 : b;
    b = b > (NBINS - 1) ? (NBINS - 1) : b;
    return b;
}

// ---- packed f32x2 helpers (sm_103a FFMA2 path) -----------------------------
__device__ __forceinline__ unsigned long long pack2(float a, float b) {
    unsigned long long r;
    asm("mov.b64 %0, {%1, %2};" : "=l"(r) : "f"(a), "f"(b));
    return r;
}
__device__ __forceinline__ void fma2(unsigned long long& acc,
                                     unsigned long long w,
                                     unsigned long long v) {
    asm("fma.rn.f32x2 %0, %1, %2, %3;" : "=l"(acc) : "l"(w), "l"(v), "l"(acc));
}
__device__ __forceinline__ void lds_u64x2(unsigned long long& a,
                                          unsigned long long& b,
                                          const float* p) {
    uint32_t ap = (uint32_t)__cvta_generic_to_shared(p);
    asm volatile("ld.shared.v2.u64 {%0,%1}, [%2];" : "=l"(a), "=l"(b) : "r"(ap));
}
__device__ __forceinline__ float ex2f(float x) {
    float r;
    asm("ex2.approx.f32 %0, %1;" : "=f"(r) : "f"(x));
    return r;
}
__device__ __forceinline__ void cpa16(const float* s, const float* g) {
    uint32_t sa = (uint32_t)__cvta_generic_to_shared(s);
    asm volatile("cp.async.cg.shared.global [%0], [%1], 16;" :: "r"(sa), "l"(g));
}
__device__ __forceinline__ void cpa4(const float* s, const float* g) {
    uint32_t sa = (uint32_t)__cvta_generic_to_shared(s);
    asm volatile("cp.async.ca.shared.global [%0], [%1], 4;" :: "r"(sa), "l"(g));
}
#define CP_COMMIT() asm volatile("cp.async.commit_group;" ::: "memory")
#define CP_WAIT1()  asm volatile("cp.async.wait_group 1;" ::: "memory")

// ---------------- K1: zero counters ----------------------------------------
__global__ void k_zero() {
    int i = blockIdx.x * blockDim.x + threadIdx.x;
    if (i < BB * NBINS) {
        (&g_qcnt[0][0])[i] = 0;
        (&g_pcnt[0][0])[i] = 0;
        (&g_qcur[0][0])[i] = 0;
        (&g_pcur[0][0])[i] = 0;
    }
}

// ---------------- K2: fused histogram (queries + points) -------------------
__global__ void k_count(const float* __restrict__ x, const float* __restrict__ xz) {
    int i = blockIdx.x * blockDim.x + threadIdx.x;
    if (i < BB * NN) {
        atomicAdd(&g_qcnt[i / NN][coord_bin(x[i])], 1);
    } else {
        int j = i - BB * NN;
        if (j < BB * MM) atomicAdd(&g_pcnt[j / MM][coord_bin(xz[j])], 1);
    }
}

// ---------------- K3: exclusive scan (shfl-based, 3 phases) ----------------
__global__ void k_scan() {  // grid = 8, block = NBINS (1024)
    __shared__ int wsum[32];
    int which = blockIdx.x;      // 0..7: first 4 = q, last 4 = p
    int b = which & 3;
    bool isq = (which < 4);
    const int* cnt = isq ? g_qcnt[b] : g_pcnt[b];
    int*       st  = isq ? g_qstart[b] : g_pstart[b];
    int t = threadIdx.x, lane = t & 31, w = t >> 5;

    int v = cnt[t];
#pragma unroll
    for (int s = 1; s < 32; s <<= 1) {
        int u = __shfl_up_sync(0xffffffffu, v, s);
        if (lane >= s) v += u;
    }
    if (lane == 31) wsum[w] = v;
    __syncthreads();
    if (w == 0) {
        int s0 = wsum[lane];
#pragma unroll
        for (int s = 1; s < 32; s <<= 1) {
            int u = __shfl_up_sync(0xffffffffu, s0, s);
            if (lane >= s) s0 += u;
        }
        wsum[lane] = s0;
    }
    __syncthreads();
    int off = (w > 0) ? wsum[w - 1] : 0;
    st[t + 1] = v + off;
    if (t == 0) st[0] = 0;
}

// ---------------- K4: fused scatter ------------------------------------------
__global__ void k_scatter(const float* __restrict__ x, const float* __restrict__ xz) {
    int i = blockIdx.x * blockDim.x + threadIdx.x;
    if (i < BB * NN) {
        int b = i / NN, n = i % NN;
        float v = x[i];
        int bn = coord_bin(v);
        int pos = g_qstart[b][bn] + atomicAdd(&g_qcur[b][bn], 1);
        g_qx[b][pos]    = v;
        g_qperm[b][pos] = n;
    } else {
        int j = i - BB * NN;
        if (j < BB * MM) {
            int b = j / MM, m = j % MM;
            float v = xz[j];
            int bn = coord_bin(v);
            int pos = g_pstart[b][bn] + atomicAdd(&g_pcur[b][bn], 1);
            g_px[b][pos]    = v;
            g_pperm[b][pos] = m;
        }
    }
}

// ---------------- K5: gather z into [B, M_sorted, C] -------------------------
__global__ void k_gather_z(const float* __restrict__ z) {
    int i = blockIdx.x * blockDim.x + threadIdx.x;
    if (i >= BB * MM) return;
    int b = i / MM, ms = i % MM;
    int mo = g_pperm[b][ms];
    const float* zb = z + (size_t)b * CC * MM + mo;
    float4* dst4 = (float4*)g_zs[b][ms];
#pragma unroll
    for (int c4 = 0; c4 < CC / 4; c4++) {
        float4 v;
        v.x = zb[(size_t)(c4 * 4 + 0) * MM];
        v.y = zb[(size_t)(c4 * 4 + 1) * MM];
        v.z = zb[(size_t)(c4 * 4 + 2) * MM];
        v.w = zb[(size_t)(c4 * 4 + 3) * MM];
        dst4[c4] = v;
    }
}

// ---------------- K6: main RBF-gather kernel --------------------------------
// Block = 32 spatially-adjacent sorted queries x 4 channel-groups (16 ch each).
// Candidate points are staged into smem tiles via cp.async double-buffering;
// inner loop per point per thread: 4 LDS.128 + 8 fma.rn.f32x2 + 1 EX2.
__global__ void __launch_bounds__(TPB) k_main(const float* __restrict__ log_scale,
                                              float* __restrict__ out) {
    __shared__ float s_px[2][PT];
    __shared__ __align__(16) float s_z[2][PT][CC];

    int blk = blockIdx.x;                 // 0 .. BB*(NN/QPB)-1 = 511
    int b   = blk >> 7;                   // NN/QPB = 128 blocks per batch
    int qb  = (blk & 127) * QPB;
    int tid = threadIdx.x;
    int q_local = tid >> 2;               // 0..31
    int cg      = tid & 3;                // 0..3

    float ls = *log_scale;
    float s  = __expf(ls);
    float c2 = -0.72134752f / (s * s);    // -0.5*log2(e)/s^2 : w = 2^(c2*d^2)
    float R  = 8.0f * s;                  // cutoff 8 sigma: weight <= 1e-14
    int kb = (int)ceilf(R * BIN_INVW);    // bins to each side (=2 here)
    if (kb < 1) kb = 1;

    float xq = g_qx[b][qb + q_local];
    // block bin range from first/last sorted query (bins are monotone)
    int blo = coord_bin(g_qx[b][qb]) - kb;            if (blo < 0) blo = 0;
    int bhi = coord_bin(g_qx[b][qb + QPB - 1]) + kb;  if (bhi > NBINS - 1) bhi = NBINS - 1;
    int plo = g_pstart[b][blo];
    int phi = g_pstart[b][bhi + 1];
    int total = phi - plo;

    unsigned long long acc[8];
#pragma unroll
    for (int j = 0; j < 8; j++) acc[j] = 0ull;   // bit pattern of (0.f, 0.f)

    int ntiles = (total + PT - 1) / PT;

    // ---- prologue: stage tile 0 -------------------------------------------
    if (ntiles > 0) {
        int base = plo;
#pragma unroll
        for (int k = 0; k < 8; k++) {             // PT*CC/4 = 1024 float4 / 128 thr
            int f = tid + k * TPB;
            int row = f >> 4, col = (f & 15) * 4;
            int sp = base + row; if (sp > MM - 1) sp = MM - 1;
            cpa16(&s_z[0][row][col], &g_zs[b][sp][col]);
        }
        if (tid < PT) {
            int sp = base + tid; if (sp > MM - 1) sp = MM - 1;
            cpa4(&s_px[0][tid], &g_px[b][sp]);
        }
    }
    CP_COMMIT();

    const float* zb_base = &s_z[0][0][cg * 16];
    const int buf_stride = PT * CC;               // floats between buffers

    for (int t = 0; t < ntiles; t++) {
        // stage tile t+1 into the other buffer
        if (t + 1 < ntiles) {
            int nb = (t + 1) & 1;
            int base = plo + (t + 1) * PT;
#pragma unroll
            for (int k = 0; k < 8; k++) {
                int f = tid + k * TPB;
                int row = f >> 4, col = (f & 15) * 4;
                int sp = base + row; if (sp > MM - 1) sp = MM - 1;
                cpa16(&s_z[nb][row][col], &g_zs[b][sp][col]);
            }
            if (tid < PT) {
                int sp = base + tid; if (sp > MM - 1) sp = MM - 1;
                cpa4(&s_px[nb][tid], &g_px[b][sp]);
            }
        }
        CP_COMMIT();
        CP_WAIT1();              // tile t's group fully landed
        __syncthreads();

        int buf = t & 1;
        int cnt = total - t * PT; if (cnt > PT) cnt = PT;
        const float* zr = zb_base + buf * buf_stride;
        const float* px = s_px[buf];

#pragma unroll 2
        for (int pp = 0; pp < cnt; pp++) {
            float d = xq - px[pp];
            float w = ex2f(c2 * d * d);
            unsigned long long w2 = pack2(w, w);
            const float* zp = zr + pp * CC;
            unsigned long long v0, v1, v2, v3, v4, v5, v6, v7;
            lds_u64x2(v0, v1, zp + 0);
            lds_u64x2(v2, v3, zp + 4);
            lds_u64x2(v4, v5, zp + 8);
            lds_u64x2(v6, v7, zp + 12);
            fma2(acc[0], w2, v0);
            fma2(acc[1], w2, v1);
            fma2(acc[2], w2, v2);
            fma2(acc[3], w2, v3);
            fma2(acc[4], w2, v4);
            fma2(acc[5], w2, v5);
            fma2(acc[6], w2, v6);
            fma2(acc[7], w2, v7);
        }
        __syncthreads();          // before next iteration overwrites buf t&1's sibling
    }

    int norig = g_qperm[b][qb + q_local];
    float* o = out + ((size_t)(b * NN + norig)) * CC + cg * 16;
    ulonglong2* o2 = (ulonglong2*)o;               // 64B-aligned
    o2[0] = make_ulonglong2(acc[0], acc[1]);
    o2[1] = make_ulonglong2(acc[2], acc[3]);
    o2[2] = make_ulonglong2(acc[4], acc[5]);
    o2[3] = make_ulonglong2(acc[6], acc[7]);
}

// ---------------- launch ------------------------------------------------------
extern "C" void kernel_launch(void* const* d_in, const int* in_sizes, int n_in,
                              void* d_out, int out_size) {
    const float* xz = (const float*)d_in[0];   // [B, M, 1]
    const float* z  = (const float*)d_in[1];   // [B, C, M]
    const float* x  = (const float*)d_in[2];   // [B, N, 1]
    const float* ls = (const float*)d_in[3];   // scalar
    float* out = (float*)d_out;                // [B, N, C]

    (void)in_sizes; (void)n_in; (void)out_size;

    int tot = BB * (NN + MM);
    k_zero<<<(BB * NBINS + 255) / 256, 256>>>();
    k_count<<<(tot + 255) / 256, 256>>>(x, xz);
    k_scan<<<8, NBINS>>>();
    k_scatter<<<(tot + 255) / 256, 256>>>(x, xz);
    k_gather_z<<<(BB * MM + 127) / 128, 128>>>(z);
    k_main<<<BB * (NN / QPB), TPB>>>(ls, out);
}

// round 7
// speedup vs baseline: 3.9720x; 1.1549x over previous
#include <cuda_runtime.h>
#include <math.h>
#include <stdint.h>

// Problem constants (fixed shapes for this problem instance).
#define BB 4
#define NN 4096
#define MM 8192
#define CC 64

// Binning over the 1D coordinate. Data ~ N(0,10^2) so [-64,64) covers
// everything; values outside clamp to edge bins (harmless: only affects
// pairs separated by >> cutoff radius).
#define NBINS 1024
#define BIN_LO (-64.0f)
#define BIN_INVW 8.0f

// Main-kernel tiling.
#define QPB 32              // sorted queries per block
#define CG  4               // channel groups of 16 channels
#define TPB (QPB * CG)      // 128 threads
#define PT  64              // candidate points per smem tile

// ---------------- scratch (no allocations allowed -> device globals) -------
__device__ int   g_pstart[BB][NBINS + 1];
__device__ int   g_qperm[BB][NN];
__device__ float g_qx   [BB][NN];
__device__ int   g_ppos [BB][MM];   // inverse perm: orig m -> sorted pos
__device__ float g_px   [BB][MM];
// z gathered into sorted-point order and transposed to [B, M, C] (8 MB).
__device__ __align__(16) float g_zs[BB][MM][CC];

__device__ __forceinline__ int coord_bin(float v) {
    int b = (int)floorf((v - BIN_LO) * BIN_INVW);
    b = b < 0 ? 0 : b;
    b = b > (NBINS - 1) ? (NBINS - 1) : b;
    return b;
}

// ---- packed f32x2 helpers (sm_103a FFMA2 path) -----------------------------
__device__ __forceinline__ unsigned long long pack2(float a, float b) {
    unsigned long long r;
    asm("mov.b64 %0, {%1, %2};" : "=l"(r) : "f"(a), "f"(b));
    return r;
}
__device__ __forceinline__ void fma2(unsigned long long& acc,
                                     unsigned long long w,
                                     unsigned long long v) {
    asm("fma.rn.f32x2 %0, %1, %2, %3;" : "=l"(acc) : "l"(w), "l"(v), "l"(acc));
}
__device__ __forceinline__ void lds_u64x2(unsigned long long& a,
                                          unsigned long long& b,
                                          const float* p) {
    uint32_t ap = (uint32_t)__cvta_generic_to_shared(p);
    asm volatile("ld.shared.v2.u64 {%0,%1}, [%2];" : "=l"(a), "=l"(b) : "r"(ap));
}
__device__ __forceinline__ float ex2f(float x) {
    float r;
    asm("ex2.approx.f32 %0, %1;" : "=f"(r) : "f"(x));
    return r;
}
__device__ __forceinline__ void cpa16(const float* s, const float* g) {
    uint32_t sa = (uint32_t)__cvta_generic_to_shared(s);
    asm volatile("cp.async.cg.shared.global [%0], [%1], 16;" :: "r"(sa), "l"(g));
}
__device__ __forceinline__ void cpa4(const float* s, const float* g) {
    uint32_t sa = (uint32_t)__cvta_generic_to_shared(s);
    asm volatile("cp.async.ca.shared.global [%0], [%1], 4;" :: "r"(sa), "l"(g));
}
#define CP_COMMIT() asm volatile("cp.async.commit_group;" ::: "memory")
#define CP_WAIT1()  asm volatile("cp.async.wait_group 1;" ::: "memory")

// ---------------- K1: fused counting-sort ------------------------------------
// grid = 8 blocks x 1024 threads. Blocks 0..3: sort queries of batch b.
// Blocks 4..7: sort points of batch b-4 (also emits inverse perm + g_pstart).
// hist -> shfl-scan -> smem-cursor scatter, all in one kernel.
__global__ void __launch_bounds__(NBINS) k_sort(const float* __restrict__ x,
                                                const float* __restrict__ xz) {
    __shared__ int hist[NBINS];       // reused as scatter cursor
    __shared__ int starts[NBINS];     // exclusive prefix (start of bin t)
    __shared__ int wsum[32];

    int which = blockIdx.x;
    bool isq = (which < BB);
    int b = which & (BB - 1);
    const float* src = isq ? (x + b * NN) : (xz + b * MM);
    int cnt = isq ? NN : MM;
    int t = threadIdx.x, lane = t & 31, w = t >> 5;

    hist[t] = 0;
    __syncthreads();

    for (int i = t; i < cnt; i += NBINS)
        atomicAdd(&hist[coord_bin(src[i])], 1);
    __syncthreads();

    // inclusive shfl scan of hist -> v; exclusive start = v - hist[t]
    int h = hist[t];
    int v = h;
#pragma unroll
    for (int s = 1; s < 32; s <<= 1) {
        int u = __shfl_up_sync(0xffffffffu, v, s);
        if (lane >= s) v += u;
    }
    if (lane == 31) wsum[w] = v;
    __syncthreads();
    if (w == 0) {
        int s0 = wsum[lane];
#pragma unroll
        for (int s = 1; s < 32; s <<= 1) {
            int u = __shfl_up_sync(0xffffffffu, s0, s);
            if (lane >= s) s0 += u;
        }
        wsum[lane] = s0;
    }
    __syncthreads();
    int incl = v + ((w > 0) ? wsum[w - 1] : 0);
    int excl = incl - h;
    starts[t] = excl;
    if (!isq) {
        g_pstart[b][t + 1] = incl;
        if (t == 0) g_pstart[b][0] = 0;
    }
    __syncthreads();
    hist[t] = starts[t];              // cursor
    __syncthreads();

    for (int i = t; i < cnt; i += NBINS) {
        float val = src[i];
        int bn = coord_bin(val);
        int pos = atomicAdd(&hist[bn], 1);
        if (isq) {
            g_qx[b][pos]   = val;
            g_qperm[b][pos] = i;
        } else {
            g_px[b][pos]  = val;
            g_ppos[b][i]  = pos;
        }
    }
}

// ---------------- K2: coalesced transpose/scatter of z -----------------------
// Block handles 32 original points x 64 channels. Reads z [B,C,M] fully
// coalesced (128B per channel-row), transposes through smem, writes each
// point's 256B channel-row to its sorted position in g_zs.
#define TM 32
__global__ void __launch_bounds__(256) k_zscatter(const float* __restrict__ z) {
    __shared__ float tile[CC][TM + 1];
    __shared__ int rowpos[TM];

    int blk = blockIdx.x;                  // BB * MM / TM = 1024 blocks
    int b   = blk >> 8;                    // MM/TM = 256 blocks per batch
    int m0  = (blk & 255) << 5;
    int t = threadIdx.x;                   // 256 threads

    const float* zb = z + (size_t)b * CC * MM + m0;
#pragma unroll
    for (int k = 0; k < 8; k++) {
        int idx = t + k * 256;             // 0..2047
        int c = idx >> 5, j = idx & 31;
        tile[c][j] = zb[(size_t)c * MM + j];
    }
    if (t < TM) rowpos[t] = g_ppos[b][m0 + t];
    __syncthreads();

#pragma unroll
    for (int k = 0; k < 2; k++) {
        int idx = t + k * 256;             // 0..511
        int j = idx >> 4, c4 = (idx & 15) << 2;
        float4 v = make_float4(tile[c4 + 0][j], tile[c4 + 1][j],
                               tile[c4 + 2][j], tile[c4 + 3][j]);
        ((float4*)g_zs[b][rowpos[j]])[idx & 15] = v;
    }
}

// ---------------- K3: main RBF-gather kernel --------------------------------
// Block = 32 spatially-adjacent sorted queries x 4 channel-groups (16 ch each).
// Candidate points staged into smem tiles via cp.async double-buffering;
// inner loop per point per thread: 4 LDS.128 + 8 fma.rn.f32x2 + 1 EX2.
__global__ void __launch_bounds__(TPB) k_main(const float* __restrict__ log_scale,
                                              float* __restrict__ out) {
    __shared__ float s_px[2][PT];
    __shared__ __align__(16) float s_z[2][PT][CC];

    int blk = blockIdx.x;                 // 0 .. BB*(NN/QPB)-1 = 511
    int b   = blk >> 7;                   // NN/QPB = 128 blocks per batch
    int qb  = (blk & 127) * QPB;
    int tid = threadIdx.x;
    int q_local = tid >> 2;               // 0..31
    int cg      = tid & 3;                // 0..3

    float ls = *log_scale;
    float s  = __expf(ls);
    float c2 = -0.72134752f / (s * s);    // -0.5*log2(e)/s^2 : w = 2^(c2*d^2)
    float R  = 8.0f * s;                  // cutoff 8 sigma: weight <= 1e-14
    int kb = (int)ceilf(R * BIN_INVW);    // bins to each side (=2 here)
    if (kb < 1) kb = 1;

    float xq = g_qx[b][qb + q_local];
    // block bin range from first/last sorted query (bins are monotone)
    int blo = coord_bin(g_qx[b][qb]) - kb;            if (blo < 0) blo = 0;
    int bhi = coord_bin(g_qx[b][qb + QPB - 1]) + kb;  if (bhi > NBINS - 1) bhi = NBINS - 1;
    int plo = g_pstart[b][blo];
    int phi = g_pstart[b][bhi + 1];
    int total = phi - plo;

    unsigned long long acc[8];
#pragma unroll
    for (int j = 0; j < 8; j++) acc[j] = 0ull;   // bit pattern of (0.f, 0.f)

    int ntiles = (total + PT - 1) / PT;

    // ---- prologue: stage tile 0 -------------------------------------------
    if (ntiles > 0) {
        int base = plo;
#pragma unroll
        for (int k = 0; k < 8; k++) {             // PT*CC/4 = 1024 float4 / 128 thr
            int f = tid + k * TPB;
            int row = f >> 4, col = (f & 15) * 4;
            int sp = base + row; if (sp > MM - 1) sp = MM - 1;
            cpa16(&s_z[0][row][col], &g_zs[b][sp][col]);
        }
        if (tid < PT) {
            int sp = base + tid; if (sp > MM - 1) sp = MM - 1;
            cpa4(&s_px[0][tid], &g_px[b][sp]);
        }
    }
    CP_COMMIT();

    const float* zb_base = &s_z[0][0][cg * 16];
    const int buf_stride = PT * CC;               // floats between buffers

    for (int t = 0; t < ntiles; t++) {
        // stage tile t+1 into the other buffer
        if (t + 1 < ntiles) {
            int nb = (t + 1) & 1;
            int base = plo + (t + 1) * PT;
#pragma unroll
            for (int k = 0; k < 8; k++) {
                int f = tid + k * TPB;
                int row = f >> 4, col = (f & 15) * 4;
                int sp = base + row; if (sp > MM - 1) sp = MM - 1;
                cpa16(&s_z[nb][row][col], &g_zs[b][sp][col]);
            }
            if (tid < PT) {
                int sp = base + tid; if (sp > MM - 1) sp = MM - 1;
                cpa4(&s_px[nb][tid], &g_px[b][sp]);
            }
        }
        CP_COMMIT();
        CP_WAIT1();              // tile t's group fully landed
        __syncthreads();

        int buf = t & 1;
        int cnt = total - t * PT; if (cnt > PT) cnt = PT;
        const float* zr = zb_base + buf * buf_stride;
        const float* px = s_px[buf];

#pragma unroll 4
        for (int pp = 0; pp < cnt; pp++) {
            float d = xq - px[pp];
            float w = ex2f(c2 * d * d);
            unsigned long long w2 = pack2(w, w);
            const float* zp = zr + pp * CC;
            unsigned long long v0, v1, v2, v3, v4, v5, v6, v7;
            lds_u64x2(v0, v1, zp + 0);
            lds_u64x2(v2, v3, zp + 4);
            lds_u64x2(v4, v5, zp + 8);
            lds_u64x2(v6, v7, zp + 12);
            fma2(acc[0], w2, v0);
            fma2(acc[1], w2, v1);
            fma2(acc[2], w2, v2);
            fma2(acc[3], w2, v3);
            fma2(acc[4], w2, v4);
            fma2(acc[5], w2, v5);
            fma2(acc[6], w2, v6);
            fma2(acc[7], w2, v7);
        }
        __syncthreads();          // before next iteration overwrites buffers
    }

    int norig = g_qperm[b][qb + q_local];
    float* o = out + ((size_t)(b * NN + norig)) * CC + cg * 16;
    ulonglong2* o2 = (ulonglong2*)o;               // 64B-aligned
    o2[0] = make_ulonglong2(acc[0], acc[1]);
    o2[1] = make_ulonglong2(acc[2], acc[3]);
    o2[2] = make_ulonglong2(acc[4], acc[5]);
    o2[3] = make_ulonglong2(acc[6], acc[7]);
}

// ---------------- launch ------------------------------------------------------
extern "C" void kernel_launch(void* const* d_in, const int* in_sizes, int n_in,
                              void* d_out, int out_size) {
    const float* xz = (const float*)d_in[0];   // [B, M, 1]
    const float* z  = (const float*)d_in[1];   // [B, C, M]
    const float* x  = (const float*)d_in[2];   // [B, N, 1]
    const float* ls = (const float*)d_in[3];   // scalar
    float* out = (float*)d_out;                // [B, N, C]

    (void)in_sizes; (void)n_in; (void)out_size;

    k_sort<<<2 * BB, NBINS>>>(x, xz);
    k_zscatter<<<BB * (MM / TM), 256>>>(z);
    k_main<<<BB * (NN / QPB), TPB>>>(ls, out);
}

// round 8
// speedup vs baseline: 3.9837x; 1.0030x over previous
#include <cuda_runtime.h>
#include <math.h>
#include <stdint.h>

// Problem constants (fixed shapes for this problem instance).
#define BB 4
#define NN 4096
#define MM 8192
#define CC 64

// Binning over the 1D coordinate. Data ~ N(0,10^2) so [-64,64) covers
// everything; values outside clamp to edge bins (harmless: only affects
// pairs separated by >> cutoff radius).
#define NBINS 1024
#define BIN_LO (-64.0f)
#define BIN_INVW 8.0f

// Main-kernel tiling.
#define QPB 32              // sorted queries per block
#define CG  4               // channel groups of 16 channels
#define TPB (QPB * CG)      // 128 threads
#define PT  64              // candidate points per smem tile

// ---------------- scratch (no allocations allowed -> device globals) -------
__device__ int   g_pstart[BB][NBINS + 1];
__device__ int   g_qperm[BB][NN];
__device__ float g_qx   [BB][NN];
__device__ int   g_ppos [BB][MM];   // inverse perm: orig m -> sorted pos
__device__ float g_px   [BB][MM];
// z gathered into sorted-point order and transposed to [B, M, C] (8 MB).
__device__ __align__(16) float g_zs[BB][MM][CC];

__device__ __forceinline__ int coord_bin(float v) {
    int b = (int)floorf((v - BIN_LO) * BIN_INVW);
    b = b < 0 ? 0 : b;
    b = b > (NBINS - 1) ? (NBINS - 1) : b;
    return b;
}

// ---- packed f32x2 helpers (sm_103a FFMA2 path) -----------------------------
// NOTE: non-volatile asm -> ptxas is free to schedule/pipeline these.
__device__ __forceinline__ unsigned long long pack2(float a, float b) {
    unsigned long long r;
    asm("mov.b64 %0, {%1, %2};" : "=l"(r) : "f"(a), "f"(b));
    return r;
}
__device__ __forceinline__ void fma2(unsigned long long& acc,
                                     unsigned long long w,
                                     unsigned long long v) {
    asm("fma.rn.f32x2 %0, %1, %2, %0;" : "+l"(acc) : "l"(w), "l"(v));
}
__device__ __forceinline__ float ex2f(float x) {
    float r;
    asm("ex2.approx.f32 %0, %1;" : "=f"(r) : "f"(x));
    return r;
}
__device__ __forceinline__ void cpa16(const float* s, const float* g) {
    uint32_t sa = (uint32_t)__cvta_generic_to_shared(s);
    asm volatile("cp.async.cg.shared.global [%0], [%1], 16;" :: "r"(sa), "l"(g));
}
__device__ __forceinline__ void cpa4(const float* s, const float* g) {
    uint32_t sa = (uint32_t)__cvta_generic_to_shared(s);
    asm volatile("cp.async.ca.shared.global [%0], [%1], 4;" :: "r"(sa), "l"(g));
}
#define CP_COMMIT() asm volatile("cp.async.commit_group;" ::: "memory")
#define CP_WAIT1()  asm volatile("cp.async.wait_group 1;" ::: "memory")

// ---------------- K1: fused counting-sort ------------------------------------
// grid = 8 blocks x 1024 threads. Blocks 0..3: sort queries of batch b.
// Blocks 4..7: sort points of batch b-4 (also emits inverse perm + g_pstart).
// hist -> shfl-scan -> smem-cursor scatter. Element loops are fully unrolled
// (cnt/NBINS = 4 or 8) with values prefetched first for MLP.
__global__ void __launch_bounds__(NBINS) k_sort(const float* __restrict__ x,
                                                const float* __restrict__ xz) {
    __shared__ int hist[NBINS];       // reused as scatter cursor
    __shared__ int wsum[32];

    int which = blockIdx.x;
    bool isq = (which < BB);
    int b = which & (BB - 1);
    const float* src = isq ? (x + b * NN) : (xz + b * MM);
    const int rounds = isq ? (NN / NBINS) : (MM / NBINS);   // 4 or 8
    int t = threadIdx.x, lane = t & 31, w = t >> 5;

    hist[t] = 0;

    // prefetch all elements this thread owns (MLP up to 8)
    float vals[8];
    int   bins[8];
#pragma unroll 8
    for (int k = 0; k < 8; k++) {
        if (k < rounds) vals[k] = src[t + k * NBINS];
    }
#pragma unroll 8
    for (int k = 0; k < 8; k++) {
        if (k < rounds) bins[k] = coord_bin(vals[k]);
    }
    __syncthreads();
#pragma unroll 8
    for (int k = 0; k < 8; k++) {
        if (k < rounds) atomicAdd(&hist[bins[k]], 1);
    }
    __syncthreads();

    // inclusive shfl scan of hist -> incl; exclusive start = incl - h
    int h = hist[t];
    int v = h;
#pragma unroll
    for (int s = 1; s < 32; s <<= 1) {
        int u = __shfl_up_sync(0xffffffffu, v, s);
        if (lane >= s) v += u;
    }
    if (lane == 31) wsum[w] = v;
    __syncthreads();
    if (w == 0) {
        int s0 = wsum[lane];
#pragma unroll
        for (int s = 1; s < 32; s <<= 1) {
            int u = __shfl_up_sync(0xffffffffu, s0, s);
            if (lane >= s) s0 += u;
        }
        wsum[lane] = s0;
    }
    __syncthreads();
    int incl = v + ((w > 0) ? wsum[w - 1] : 0);
    int excl = incl - h;
    if (!isq) {
        g_pstart[b][t + 1] = incl;
        if (t == 0) g_pstart[b][0] = 0;
    }
    __syncthreads();          // everyone done reading hist[] as counts
    hist[t] = excl;           // cursor
    __syncthreads();

    // scatter: 8 independent atomic->store chains per thread (MLP)
    int pos[8];
#pragma unroll 8
    for (int k = 0; k < 8; k++) {
        if (k < rounds) pos[k] = atomicAdd(&hist[bins[k]], 1);
    }
    if (isq) {
#pragma unroll 8
        for (int k = 0; k < 8; k++) {
            if (k < rounds) {
                g_qx[b][pos[k]]    = vals[k];
                g_qperm[b][pos[k]] = t + k * NBINS;
            }
        }
    } else {
#pragma unroll 8
        for (int k = 0; k < 8; k++) {
            if (k < rounds) {
                g_px[b][pos[k]]        = vals[k];
                g_ppos[b][t + k * NBINS] = pos[k];
            }
        }
    }
}

// ---------------- K2: coalesced transpose/scatter of z -----------------------
// Block handles 32 original points x 64 channels. Reads z [B,C,M] fully
// coalesced (128B per channel-row), transposes through smem, writes each
// point's 256B channel-row to its sorted position in g_zs.
#define TM 32
__global__ void __launch_bounds__(256) k_zscatter(const float* __restrict__ z) {
    __shared__ float tile[CC][TM + 1];
    __shared__ int rowpos[TM];

    int blk = blockIdx.x;                  // BB * MM / TM = 1024 blocks
    int b   = blk >> 8;                    // MM/TM = 256 blocks per batch
    int m0  = (blk & 255) << 5;
    int t = threadIdx.x;                   // 256 threads

    const float* zb = z + (size_t)b * CC * MM + m0;
#pragma unroll
    for (int k = 0; k < 8; k++) {
        int idx = t + k * 256;             // 0..2047
        int c = idx >> 5, j = idx & 31;
        tile[c][j] = zb[(size_t)c * MM + j];
    }
    if (t < TM) rowpos[t] = g_ppos[b][m0 + t];
    __syncthreads();

#pragma unroll
    for (int k = 0; k < 2; k++) {
        int idx = t + k * 256;             // 0..511
        int j = idx >> 4, c4 = (idx & 15) << 2;
        float4 v = make_float4(tile[c4 + 0][j], tile[c4 + 1][j],
                               tile[c4 + 2][j], tile[c4 + 3][j]);
        ((float4*)g_zs[b][rowpos[j]])[idx & 15] = v;
    }
}

// ---------------- K3: main RBF-gather kernel --------------------------------
// Block = 32 spatially-adjacent sorted queries x 4 channel-groups (16 ch each).
// Candidate points staged into smem tiles via cp.async double-buffering;
// compute loop uses plain (schedulable) LDS.128 + fma.rn.f32x2 so ptxas can
// software-pipeline EX2/LDS latency across points.
__global__ void __launch_bounds__(TPB) k_main(const float* __restrict__ log_scale,
                                              float* __restrict__ out) {
    __shared__ float s_px[2][PT];
    __shared__ __align__(16) float s_z[2][PT][CC];

    int blk = blockIdx.x;                 // 0 .. BB*(NN/QPB)-1 = 511
    int b   = blk >> 7;                   // NN/QPB = 128 blocks per batch
    int qb  = (blk & 127) * QPB;
    int tid = threadIdx.x;
    int q_local = tid >> 2;               // 0..31
    int cg      = tid & 3;                // 0..3

    float ls = *log_scale;
    float s  = __expf(ls);
    float c2 = -0.72134752f / (s * s);    // -0.5*log2(e)/s^2 : w = 2^(c2*d^2)
    float R  = 8.0f * s;                  // cutoff 8 sigma: weight <= 1e-14
    int kb = (int)ceilf(R * BIN_INVW);    // bins to each side (=2 here)
    if (kb < 1) kb = 1;

    float xq = g_qx[b][qb + q_local];
    // block bin range from first/last sorted query (bins are monotone)
    int blo = coord_bin(g_qx[b][qb]) - kb;            if (blo < 0) blo = 0;
    int bhi = coord_bin(g_qx[b][qb + QPB - 1]) + kb;  if (bhi > NBINS - 1) bhi = NBINS - 1;
    int plo = g_pstart[b][blo];
    int phi = g_pstart[b][bhi + 1];
    int total = phi - plo;

    unsigned long long acc[8];
#pragma unroll
    for (int j = 0; j < 8; j++) acc[j] = 0ull;   // bit pattern of (0.f, 0.f)

    int ntiles = (total + PT - 1) / PT;

    // ---- prologue: stage tile 0 -------------------------------------------
    if (ntiles > 0) {
        int base = plo;
#pragma unroll
        for (int k = 0; k < 8; k++) {             // PT*CC/4 = 1024 float4 / 128 thr
            int f = tid + k * TPB;
            int row = f >> 4, col = (f & 15) * 4;
            int sp = base + row; if (sp > MM - 1) sp = MM - 1;
            cpa16(&s_z[0][row][col], &g_zs[b][sp][col]);
        }
        if (tid < PT) {
            int sp = base + tid; if (sp > MM - 1) sp = MM - 1;
            cpa4(&s_px[0][tid], &g_px[b][sp]);
        }
    }
    CP_COMMIT();

    for (int t = 0; t < ntiles; t++) {
        // stage tile t+1 into the other buffer
        if (t + 1 < ntiles) {
            int nb = (t + 1) & 1;
            int base = plo + (t + 1) * PT;
#pragma unroll
            for (int k = 0; k < 8; k++) {
                int f = tid + k * TPB;
                int row = f >> 4, col = (f & 15) * 4;
                int sp = base + row; if (sp > MM - 1) sp = MM - 1;
                cpa16(&s_z[nb][row][col], &g_zs[b][sp][col]);
            }
            if (tid < PT) {
                int sp = base + tid; if (sp > MM - 1) sp = MM - 1;
                cpa4(&s_px[nb][tid], &g_px[b][sp]);
            }
        }
        CP_COMMIT();
        CP_WAIT1();              // tile t's group fully landed
        __syncthreads();

        int buf = t & 1;
        int cnt = total - t * PT; if (cnt > PT) cnt = PT;
        // schedulable smem pointers (static shared -> LDS)
        const float* px = s_px[buf];
        const ulonglong2* zr = (const ulonglong2*)(&s_z[buf][0][0]) + cg * 4;

#pragma unroll 8
        for (int pp = 0; pp < cnt; pp++) {
            float d = xq - px[pp];
            float w = ex2f(c2 * d * d);
            unsigned long long w2 = pack2(w, w);
            const ulonglong2* zp = zr + pp * (CC / 4);
            ulonglong2 a0 = zp[0];
            ulonglong2 a1 = zp[1];
            ulonglong2 a2 = zp[2];
            ulonglong2 a3 = zp[3];
            fma2(acc[0], w2, a0.x);
            fma2(acc[1], w2, a0.y);
            fma2(acc[2], w2, a1.x);
            fma2(acc[3], w2, a1.y);
            fma2(acc[4], w2, a2.x);
            fma2(acc[5], w2, a2.y);
            fma2(acc[6], w2, a3.x);
            fma2(acc[7], w2, a3.y);
        }
        __syncthreads();          // before next iteration overwrites buffers
    }

    int norig = g_qperm[b][qb + q_local];
    float* o = out + ((size_t)(b * NN + norig)) * CC + cg * 16;
    ulonglong2* o2 = (ulonglong2*)o;               // 64B-aligned
    o2[0] = make_ulonglong2(acc[0], acc[1]);
    o2[1] = make_ulonglong2(acc[2], acc[3]);
    o2[2] = make_ulonglong2(acc[4], acc[5]);
    o2[3] = make_ulonglong2(acc[6], acc[7]);
}

// ---------------- launch ------------------------------------------------------
extern "C" void kernel_launch(void* const* d_in, const int* in_sizes, int n_in,
                              void* d_out, int out_size) {
    const float* xz = (const float*)d_in[0];   // [B, M, 1]
    const float* z  = (const float*)d_in[1];   // [B, C, M]
    const float* x  = (const float*)d_in[2];   // [B, N, 1]
    const float* ls = (const float*)d_in[3];   // scalar
    float* out = (float*)d_out;                // [B, N, C]

    (void)in_sizes; (void)n_in; (void)out_size;

    k_sort<<<2 * BB, NBINS>>>(x, xz);
    k_zscatter<<<BB * (MM / TM), 256>>>(z);
    k_main<<<BB * (NN / QPB), TPB>>>(ls, out);
}